// round 1
// baseline (speedup 1.0000x reference)
#include <cuda_runtime.h>
#include <cstdint>

#define B_N  32
#define C_IN 64
#define H    192
#define W    192
#define HO   190
#define WO   190
#define OC   128
#define HW   (H*W)
#define TPB  256

// ---------------- device scratch (static: no allocations allowed) ----------
__device__ float g_valid[B_N][4];        // 1.0 if fixation valid else 0.0
__device__ float g_bsum[B_N][OC];        // sum_f valid[b,f]*bias[f,oc]
__device__ float g_wT[C_IN * 9 * OC];    // wT[(c*9+kk)*128 + oc] = weight[f,oc,j,ky,kx]

// NaN test immune to fast-math
__device__ __forceinline__ bool is_nan_bits(float v) {
    unsigned u = __float_as_uint(v);
    return (u & 0x7fffffffu) > 0x7f800000u;
}

// ---------------- packed f32x2 helpers ------------------------------------
typedef unsigned long long u64;

__device__ __forceinline__ u64 pack2(float lo, float hi) {
    u64 r;
    asm("mov.b64 %0, {%1, %2};" : "=l"(r) : "f"(lo), "f"(hi));
    return r;
}
__device__ __forceinline__ void unpack2(u64 v, float& lo, float& hi) {
    asm("mov.b64 {%0, %1}, %2;" : "=f"(lo), "=f"(hi) : "l"(v));
}
__device__ __forceinline__ void ffma2(u64& d, u64 a, u64 b) {
    asm("fma.rn.f32x2 %0, %1, %2, %0;" : "+l"(d) : "l"(a), "l"(b));
}

// ---------------- prep: validity mask + masked bias sum --------------------
__global__ void prep_kernel(const float* __restrict__ x, const float* __restrict__ bias) {
    __shared__ float sval[B_N][4];
    int t = threadIdx.x;
    if (t < B_N * 4) {
        int b = t >> 2, f = t & 3;
        float v = x[(size_t)(b * C_IN + f) * HW];   // marker at (0,0) of channel f
        float val = is_nan_bits(v) ? 0.f : 1.f;
        g_valid[b][f] = val;
        sval[b][f] = val;
    }
    __syncthreads();
    for (int i = t; i < B_N * OC; i += TPB) {
        int b = i >> 7, oc = i & 127;
        float s = 0.f;
#pragma unroll
        for (int f = 0; f < 4; f++) s += sval[b][f] * bias[f * OC + oc];
        g_bsum[b][oc] = s;
    }
}

// ---------------- weight transpose to coalesced layout ---------------------
// weight[f][oc][j][ky][kx] (f*18432 + oc*144 + j*9 + ky*3 + kx)
//   -> g_wT[(c*9 + kk)*128 + oc],  c = j*4 + f,  kk = ky*3 + kx
__global__ void wtrans_kernel(const float* __restrict__ w) {
    int i = blockIdx.x * blockDim.x + threadIdx.x;   // 288*256 == 73728 exactly
    int oc = i & 127;
    int kk = (i >> 7) % 9;
    int c  = i / (9 * 128);
    int f = c & 3, j = c >> 2;
    g_wT[i] = w[f * 18432 + oc * 144 + j * 9 + kk];
}

// ---------------- main conv: 64oc x 64px tile per block --------------------
// grid = (3 x-tiles, 190 rows, 32 batches * 2 oc-tiles), block = 256
__global__ void __launch_bounds__(TPB, 2)
conv_kernel(const float* __restrict__ x, float* __restrict__ out) {
    const int x0  = blockIdx.x * 64;       // 0, 64, 128
    const int y   = blockIdx.y;            // 0..189
    const int b   = blockIdx.z >> 1;
    const int oc0 = (blockIdx.z & 1) * 64;

    __shared__ float As[9][64];            // weights for current channel
    __shared__ float Bs[3][66];            // 3 input rows, 66 cols
    __shared__ float vmask[4];

    const int t   = threadIdx.x;
    const int tx  = t & 15;                // pixel group
    const int ty  = t >> 4;                // oc group
    const int pxl = tx * 4;                // local pixel base (0..60)
    const int ocl = ty * 4;                // local oc base  (0..60)

    if (t < 4) vmask[t] = g_valid[b][t];

    // B-tile load assignment (constant per thread)
    const int bky  = t / 66;               // only t<198 load
    const int bcol = t - bky * 66;
    const int nload = min(66, W - x0);     // 66,66,64 for the 3 x-tiles

    // acc[p][q]: pixel pxl+p, oc pair (oc0+ocl+2q, oc0+ocl+2q+1), packed f32x2
    u64 acc[4][2];
#pragma unroll
    for (int p = 0; p < 4; p++) { acc[p][0] = 0ull; acc[p][1] = 0ull; }

    const float* xb = x + (size_t)b * C_IN * HW;

#pragma unroll 1
    for (int c = 0; c < C_IN; c++) {
        const int f = c & 3;
        const float* wsrc = g_wT + (c * 9) * 128 + oc0;
        const float* xc   = xb + (size_t)c * HW + (size_t)y * W + x0;

        __syncthreads();   // previous iteration's reads of As/Bs are done

        // load weight slice (coalesced: consecutive i -> consecutive oc)
        for (int i = t; i < 576; i += TPB) {
            As[i >> 6][i & 63] = wsrc[(i >> 6) * 128 + (i & 63)];
        }
        // load 3 input rows, masked (nan->0, invalid fixation -> 0)
        if (t < 198) {
            float v = 0.f;
            if (bcol < nload) {
                v = xc[bky * W + bcol];
                v = is_nan_bits(v) ? 0.f : v;
                v *= vmask[f];
            }
            Bs[bky][bcol] = v;
        }
        __syncthreads();

#pragma unroll
        for (int ky = 0; ky < 3; ky++) {
            u64 s[6];
#pragma unroll
            for (int i = 0; i < 6; i++) {
                float bv = Bs[ky][pxl + i];
                s[i] = pack2(bv, bv);
            }
#pragma unroll
            for (int kx = 0; kx < 3; kx++) {
                const u64* ap = reinterpret_cast<const u64*>(&As[ky * 3 + kx][ocl]);
                u64 a0 = ap[0];                 // weights (oc, oc+1)
                u64 a1 = ap[1];                 // weights (oc+2, oc+3)
#pragma unroll
                for (int p = 0; p < 4; p++) {
                    ffma2(acc[p][0], a0, s[kx + p]);
                    ffma2(acc[p][1], a1, s[kx + p]);
                }
            }
        }
    }

    // ---------------- epilogue: add masked bias, store -----------------------
    float bs[4];
#pragma unroll
    for (int i = 0; i < 4; i++) bs[i] = g_bsum[b][oc0 + ocl + i];

#pragma unroll
    for (int q = 0; q < 2; q++) {
#pragma unroll
        for (int hh = 0; hh < 2; hh++) {
            int oc = oc0 + ocl + 2 * q + hh;
            float* orow = out + ((size_t)(b * OC + oc) * HO + y) * WO + x0 + pxl;
            float v[4];
#pragma unroll
            for (int p = 0; p < 4; p++) {
                float lo, hi;
                unpack2(acc[p][q], lo, hi);
                v[p] = (hh == 0 ? lo : hi) + bs[2 * q + hh];
            }
            // px pairs never straddle WO=190 (even); element offsets are even -> 8B aligned
            if (x0 + pxl < WO)
                *reinterpret_cast<float2*>(orow) = make_float2(v[0], v[1]);
            if (x0 + pxl + 2 < WO)
                *reinterpret_cast<float2*>(orow + 2) = make_float2(v[2], v[3]);
        }
    }
}

// ---------------- launch ----------------------------------------------------
extern "C" void kernel_launch(void* const* d_in, const int* in_sizes, int n_in,
                              void* d_out, int out_size) {
    const float* x    = (const float*)d_in[0];
    const float* w    = (const float*)d_in[1];
    const float* bias = (const float*)d_in[2];
    float* out = (float*)d_out;

    prep_kernel<<<1, TPB>>>(x, bias);
    wtrans_kernel<<<288, TPB>>>(w);                 // 288*256 == 73728 weights
    conv_kernel<<<dim3(3, HO, B_N * 2), TPB>>>(x, out);
}

// round 2
// speedup vs baseline: 2.3130x; 2.3130x over previous
#include <cuda_runtime.h>
#include <cstdint>

#define B_N  32
#define C_IN 64
#define H    192
#define W    192
#define HO   190
#define WO   190
#define OC   128
#define HW   (H*W)

// ---------------- device scratch (no allocations allowed) -------------------
__device__ float g_valid[B_N][4];        // 1.0 if fixation valid else 0.0
__device__ float g_bsum[B_N][OC];        // sum_f valid[b,f]*bias[f,oc]
__device__ float g_wT[C_IN * 9 * OC];    // wT[(c*9+kk)*128 + oc]

// NaN test immune to fast-math
__device__ __forceinline__ bool is_nan_bits(float v) {
    unsigned u = __float_as_uint(v);
    return (u & 0x7fffffffu) > 0x7f800000u;
}

// ---------------- packed f32x2 helpers --------------------------------------
typedef unsigned long long u64;

__device__ __forceinline__ u64 pack2(float lo, float hi) {
    u64 r;
    asm("mov.b64 %0, {%1, %2};" : "=l"(r) : "f"(lo), "f"(hi));
    return r;
}
__device__ __forceinline__ void unpack2(u64 v, float& lo, float& hi) {
    asm("mov.b64 {%0, %1}, %2;" : "=f"(lo), "=f"(hi) : "l"(v));
}
__device__ __forceinline__ void ffma2(u64& d, u64 a, u64 b) {
    asm("fma.rn.f32x2 %0, %1, %2, %0;" : "+l"(d) : "l"(a), "l"(b));
}

// ---------------- setup: validity + bias sums + weight transpose ------------
// grid 289 blocks x 256: blocks 0..287 transpose weights, block 288 does prep.
__global__ void setup_kernel(const float* __restrict__ x,
                             const float* __restrict__ w,
                             const float* __restrict__ bias) {
    int t = threadIdx.x;
    if (blockIdx.x < 288) {
        int i = blockIdx.x * 256 + t;                // 73728 weights exactly
        int oc = i & 127;
        int kk = (i >> 7) % 9;
        int c  = i / (9 * 128);
        int f = c & 3, j = c >> 2;
        // weight[f][oc][j][ky][kx] -> g_wT[(c*9+kk)*128 + oc]
        g_wT[i] = w[f * 18432 + oc * 144 + j * 9 + kk];
    } else {
        __shared__ float sval[B_N][4];
        if (t < B_N * 4) {
            int b = t >> 2, f = t & 3;
            float v = x[(size_t)(b * C_IN + f) * HW];     // marker at (0,0)
            float val = is_nan_bits(v) ? 0.f : 1.f;
            g_valid[b][f] = val;
            sval[b][f] = val;
        }
        __syncthreads();
        for (int i = t; i < B_N * OC; i += 256) {
            int b = i >> 7, oc = i & 127;
            float s = 0.f;
#pragma unroll
            for (int f = 0; f < 4; f++) s += sval[b][f] * bias[f * OC + oc];
            g_bsum[b][oc] = s;
        }
    }
}

// ---------------- main conv: 64px x 64oc x 2rows tile, pipelined ------------
// grid = (3 x-tiles, 95 row-pairs, 32 batches * 2 oc-tiles), block = 256
__global__ void __launch_bounds__(256, 2)
conv_kernel(const float* __restrict__ x, float* __restrict__ out) {
    const int x0  = blockIdx.x * 64;          // 0, 64, 128
    const int y0  = blockIdx.y * 2;           // output rows y0, y0+1
    const int b   = blockIdx.z >> 1;
    const int oc0 = (blockIdx.z & 1) * 64;

    __shared__ float Ws[2][9][64];            // double-buffered weight slice
    __shared__ float Xs[2][4][66];            // double-buffered 4 input rows
    __shared__ float vm[4];

    const int t   = threadIdx.x;
    const int tx  = t & 15;
    const int ty  = t >> 4;
    const int pxl = tx * 4;                   // local pixel base
    const int ocl = ty * 4;                   // local oc base

    const int nload = min(66, W - x0);        // 66,66,64
    const int irow  = t / 66;                 // input-load row   (t<264)
    const int icol  = t - irow * 66;          // input-load col

    const float* xb = x + (size_t)b * C_IN * HW + (size_t)y0 * W + x0;

    if (t < 4) vm[t] = g_valid[b][t];
    __syncthreads();

    float w0, w1, w2 = 0.f, xv0, xv1;

    // -------- prologue: load channel 0 into buffer 0 --------
    {
        const float* wsrc = g_wT + oc0;       // channel 0
        w0 = wsrc[(t >> 6) * 128 + (t & 63)];
        w1 = wsrc[((t >> 6) + 4) * 128 + (t & 63)];
        if (t < 64) w2 = wsrc[8 * 128 + t];
        float vmf = vm[0];
        float v = 0.f;
        if (t < 264 && icol < nload) {
            v = xb[irow * W + icol];
            v = is_nan_bits(v) ? 0.f : v;
            v *= vmf;
        }
        xv0 = v;
        v = 0.f;
        if (t < 8 && (t + 58) < nload) {
            v = xb[3 * W + t + 58];
            v = is_nan_bits(v) ? 0.f : v;
            v *= vmf;
        }
        xv1 = v;

        float* Wn = (float*)Ws[0];
        float* Xn = (float*)Xs[0];
        Wn[t] = w0; Wn[t + 256] = w1;
        if (t < 64) Wn[t + 512] = w2;
        if (t < 264) Xn[t] = xv0;
        if (t < 8)   Xn[t + 256] = xv1;
    }
    __syncthreads();

    // acc[y][p][q]: row y0+y, pixel pxl+p, oc pair (ocl+2q, ocl+2q+1)
    u64 acc[2][4][2];
#pragma unroll
    for (int yy = 0; yy < 2; yy++)
#pragma unroll
        for (int p = 0; p < 4; p++) { acc[yy][p][0] = 0ull; acc[yy][p][1] = 0ull; }

#pragma unroll 1
    for (int c = 0; c < C_IN; c++) {
        const int buf = c & 1;
        const int cn  = c + 1;

        // -------- prefetch channel c+1 into registers --------
        if (cn < C_IN) {
            const float* wsrc = g_wT + cn * 9 * 128 + oc0;
            w0 = wsrc[(t >> 6) * 128 + (t & 63)];
            w1 = wsrc[((t >> 6) + 4) * 128 + (t & 63)];
            if (t < 64) w2 = wsrc[8 * 128 + t];
            const float* xc = xb + (size_t)cn * HW;
            float vmf = vm[cn & 3];
            float v = 0.f;
            if (t < 264 && icol < nload) {
                v = xc[irow * W + icol];
                v = is_nan_bits(v) ? 0.f : v;
                v *= vmf;
            }
            xv0 = v;
            v = 0.f;
            if (t < 8 && (t + 58) < nload) {
                v = xc[3 * W + t + 58];
                v = is_nan_bits(v) ? 0.f : v;
                v *= vmf;
            }
            xv1 = v;
        }

        // -------- compute channel c --------
        const float (*Wb)[64] = Ws[buf];
        const float (*Xb)[66] = Xs[buf];
#pragma unroll
        for (int ky = 0; ky < 3; ky++) {
            u64 s[2][6];
#pragma unroll
            for (int yy = 0; yy < 2; yy++)
#pragma unroll
                for (int i = 0; i < 6; i++) {
                    float v = Xb[ky + yy][pxl + i];
                    s[yy][i] = pack2(v, v);
                }
#pragma unroll
            for (int kx = 0; kx < 3; kx++) {
                const u64* ap = reinterpret_cast<const u64*>(&Wb[ky * 3 + kx][ocl]);
                u64 a0 = ap[0];
                u64 a1 = ap[1];
#pragma unroll
                for (int yy = 0; yy < 2; yy++)
#pragma unroll
                    for (int p = 0; p < 4; p++) {
                        ffma2(acc[yy][p][0], a0, s[yy][kx + p]);
                        ffma2(acc[yy][p][1], a1, s[yy][kx + p]);
                    }
            }
        }

        // -------- store prefetch into the other buffer --------
        if (cn < C_IN) {
            float* Wn = (float*)Ws[buf ^ 1];
            float* Xn = (float*)Xs[buf ^ 1];
            Wn[t] = w0; Wn[t + 256] = w1;
            if (t < 64) Wn[t + 512] = w2;
            if (t < 264) Xn[t] = xv0;
            if (t < 8)   Xn[t + 256] = xv1;
        }
        __syncthreads();
    }

    // ---------------- epilogue: add masked bias, store -----------------------
    float bs[4];
#pragma unroll
    for (int i = 0; i < 4; i++) bs[i] = g_bsum[b][oc0 + ocl + i];

#pragma unroll
    for (int yy = 0; yy < 2; yy++) {
        const int yrow = y0 + yy;
#pragma unroll
        for (int q = 0; q < 2; q++) {
#pragma unroll
            for (int hh = 0; hh < 2; hh++) {
                int oc = oc0 + ocl + 2 * q + hh;
                float* orow = out + ((size_t)(b * OC + oc) * HO + yrow) * WO + x0 + pxl;
                float v[4];
#pragma unroll
                for (int p = 0; p < 4; p++) {
                    float lo, hi;
                    unpack2(acc[yy][p][q], lo, hi);
                    v[p] = (hh == 0 ? lo : hi) + bs[2 * q + hh];
                }
                if (x0 + pxl < WO)
                    *reinterpret_cast<float2*>(orow) = make_float2(v[0], v[1]);
                if (x0 + pxl + 2 < WO)
                    *reinterpret_cast<float2*>(orow + 2) = make_float2(v[2], v[3]);
            }
        }
    }
}

// ---------------- launch -----------------------------------------------------
extern "C" void kernel_launch(void* const* d_in, const int* in_sizes, int n_in,
                              void* d_out, int out_size) {
    const float* x    = (const float*)d_in[0];
    const float* w    = (const float*)d_in[1];
    const float* bias = (const float*)d_in[2];
    float* out = (float*)d_out;

    setup_kernel<<<289, 256>>>(x, w, bias);
    conv_kernel<<<dim3(3, 95, 64), 256>>>(x, out);
}

// round 3
// speedup vs baseline: 2.3205x; 1.0033x over previous
#include <cuda_runtime.h>
#include <cstdint>

#define B_N  32
#define C_IN 64
#define H    192
#define W    192
#define HO   190
#define WO   190
#define OC   128
#define HW   (H*W)

// ---------------- device scratch (no allocations allowed) -------------------
__device__ float g_valid[B_N][4];        // 1.0 if fixation valid else 0.0
__device__ float g_bsum[B_N][OC];        // sum_f valid[b,f]*bias[f,oc]
__device__ float g_wT[C_IN * 9 * OC];    // wT[(c*9+kk)*128 + oc]

// NaN test immune to fast-math
__device__ __forceinline__ bool is_nan_bits(float v) {
    unsigned u = __float_as_uint(v);
    return (u & 0x7fffffffu) > 0x7f800000u;
}

// ---------------- packed f32x2 helpers --------------------------------------
typedef unsigned long long u64;

__device__ __forceinline__ u64 pack2(float lo, float hi) {
    u64 r;
    asm("mov.b64 %0, {%1, %2};" : "=l"(r) : "f"(lo), "f"(hi));
    return r;
}
__device__ __forceinline__ void unpack2(u64 v, float& lo, float& hi) {
    asm("mov.b64 {%0, %1}, %2;" : "=f"(lo), "=f"(hi) : "l"(v));
}
__device__ __forceinline__ void ffma2(u64& d, u64 a, u64 b) {
    asm("fma.rn.f32x2 %0, %1, %2, %0;" : "+l"(d) : "l"(a), "l"(b));
}

// ---------------- setup: validity + bias sums + weight transpose ------------
// grid 289 blocks x 256: blocks 0..287 transpose weights, block 288 does prep.
__global__ void setup_kernel(const float* __restrict__ x,
                             const float* __restrict__ w,
                             const float* __restrict__ bias) {
    int t = threadIdx.x;
    if (blockIdx.x < 288) {
        int i = blockIdx.x * 256 + t;                // 73728 weights exactly
        int oc = i & 127;
        int kk = (i >> 7) % 9;
        int c  = i / (9 * 128);
        int f = c & 3, j = c >> 2;
        // weight[f][oc][j][ky][kx] -> g_wT[(c*9+kk)*128 + oc]
        g_wT[i] = w[f * 18432 + oc * 144 + j * 9 + kk];
    } else {
        __shared__ float sval[B_N][4];
        if (t < B_N * 4) {
            int b = t >> 2, f = t & 3;
            float v = x[(size_t)(b * C_IN + f) * HW];     // marker at (0,0)
            float val = is_nan_bits(v) ? 0.f : 1.f;
            g_valid[b][f] = val;
            sval[b][f] = val;
        }
        __syncthreads();
        for (int i = t; i < B_N * OC; i += 256) {
            int b = i >> 7, oc = i & 127;
            float s = 0.f;
#pragma unroll
            for (int f = 0; f < 4; f++) s += sval[b][f] * bias[f * OC + oc];
            g_bsum[b][oc] = s;
        }
    }
}

// ---------------- main conv: 64px x 64oc x 2rows tile, pipelined ------------
// grid = (3 x-tiles, 95 row-pairs, 32 batches * 2 oc-tiles), block = 256
__global__ void __launch_bounds__(256, 2)
conv_kernel(const float* __restrict__ x, float* __restrict__ out) {
    const int x0  = blockIdx.x * 64;          // 0, 64, 128
    const int y0  = blockIdx.y * 2;           // output rows y0, y0+1
    const int b   = blockIdx.z >> 1;
    const int oc0 = (blockIdx.z & 1) * 64;

    __shared__ float Ws[2][9][64];            // double-buffered weight slice
    __shared__ float Xs[2][4][66];            // double-buffered 4 input rows
    __shared__ float vm[4];

    const int t   = threadIdx.x;
    const int tx  = t & 15;
    const int ty  = t >> 4;
    const int pxl = tx * 4;                   // local pixel base
    const int ocl = ty * 4;                   // local oc base

    const int nload = min(66, W - x0);        // 66,66,64
    const int irow  = t / 66;                 // input-load row   (t<264)
    const int icol  = t - irow * 66;          // input-load col

    const float* xb = x + (size_t)b * C_IN * HW + (size_t)y0 * W + x0;

    if (t < 4) vm[t] = g_valid[b][t];
    __syncthreads();

    float w0, w1, w2 = 0.f, xv0, xv1;

    // -------- prologue: load channel 0 into buffer 0 --------
    {
        const float* wsrc = g_wT + oc0;       // channel 0
        w0 = wsrc[(t >> 6) * 128 + (t & 63)];
        w1 = wsrc[((t >> 6) + 4) * 128 + (t & 63)];
        if (t < 64) w2 = wsrc[8 * 128 + t];
        float vmf = vm[0];
        float v = 0.f;
        if (t < 264 && icol < nload) {
            v = xb[irow * W + icol];
            v = is_nan_bits(v) ? 0.f : v;
            v *= vmf;
        }
        xv0 = v;
        v = 0.f;
        if (t < 8 && (t + 58) < nload) {
            v = xb[3 * W + t + 58];
            v = is_nan_bits(v) ? 0.f : v;
            v *= vmf;
        }
        xv1 = v;

        float* Wn = (float*)Ws[0];
        float* Xn = (float*)Xs[0];
        Wn[t] = w0; Wn[t + 256] = w1;
        if (t < 64) Wn[t + 512] = w2;
        if (t < 264) Xn[t] = xv0;
        if (t < 8)   Xn[t + 256] = xv1;
    }
    __syncthreads();

    // acc[y][p][q]: row y0+y, pixel pxl+p, oc pair (ocl+2q, ocl+2q+1)
    u64 acc[2][4][2];
#pragma unroll
    for (int yy = 0; yy < 2; yy++)
#pragma unroll
        for (int p = 0; p < 4; p++) { acc[yy][p][0] = 0ull; acc[yy][p][1] = 0ull; }

#pragma unroll 1
    for (int c = 0; c < C_IN; c++) {
        const int buf = c & 1;
        const int cn  = c + 1;

        // -------- prefetch channel c+1 into registers --------
        if (cn < C_IN) {
            const float* wsrc = g_wT + cn * 9 * 128 + oc0;
            w0 = wsrc[(t >> 6) * 128 + (t & 63)];
            w1 = wsrc[((t >> 6) + 4) * 128 + (t & 63)];
            if (t < 64) w2 = wsrc[8 * 128 + t];
            const float* xc = xb + (size_t)cn * HW;
            float vmf = vm[cn & 3];
            float v = 0.f;
            if (t < 264 && icol < nload) {
                v = xc[irow * W + icol];
                v = is_nan_bits(v) ? 0.f : v;
                v *= vmf;
            }
            xv0 = v;
            v = 0.f;
            if (t < 8 && (t + 58) < nload) {
                v = xc[3 * W + t + 58];
                v = is_nan_bits(v) ? 0.f : v;
                v *= vmf;
            }
            xv1 = v;
        }

        // -------- compute channel c --------
        const float (*Wb)[64] = Ws[buf];
        const float (*Xb)[66] = Xs[buf];
#pragma unroll
        for (int ky = 0; ky < 3; ky++) {
            u64 s[2][6];
#pragma unroll
            for (int yy = 0; yy < 2; yy++)
#pragma unroll
                for (int i = 0; i < 6; i++) {
                    float v = Xb[ky + yy][pxl + i];
                    s[yy][i] = pack2(v, v);
                }
#pragma unroll
            for (int kx = 0; kx < 3; kx++) {
                const u64* ap = reinterpret_cast<const u64*>(&Wb[ky * 3 + kx][ocl]);
                u64 a0 = ap[0];
                u64 a1 = ap[1];
#pragma unroll
                for (int yy = 0; yy < 2; yy++)
#pragma unroll
                    for (int p = 0; p < 4; p++) {
                        ffma2(acc[yy][p][0], a0, s[yy][kx + p]);
                        ffma2(acc[yy][p][1], a1, s[yy][kx + p]);
                    }
            }
        }

        // -------- store prefetch into the other buffer --------
        if (cn < C_IN) {
            float* Wn = (float*)Ws[buf ^ 1];
            float* Xn = (float*)Xs[buf ^ 1];
            Wn[t] = w0; Wn[t + 256] = w1;
            if (t < 64) Wn[t + 512] = w2;
            if (t < 264) Xn[t] = xv0;
            if (t < 8)   Xn[t + 256] = xv1;
        }
        __syncthreads();
    }

    // ---------------- epilogue: add masked bias, store -----------------------
    float bs[4];
#pragma unroll
    for (int i = 0; i < 4; i++) bs[i] = g_bsum[b][oc0 + ocl + i];

#pragma unroll
    for (int yy = 0; yy < 2; yy++) {
        const int yrow = y0 + yy;
#pragma unroll
        for (int q = 0; q < 2; q++) {
#pragma unroll
            for (int hh = 0; hh < 2; hh++) {
                int oc = oc0 + ocl + 2 * q + hh;
                float* orow = out + ((size_t)(b * OC + oc) * HO + yrow) * WO + x0 + pxl;
                float v[4];
#pragma unroll
                for (int p = 0; p < 4; p++) {
                    float lo, hi;
                    unpack2(acc[yy][p][q], lo, hi);
                    v[p] = (hh == 0 ? lo : hi) + bs[2 * q + hh];
                }
                if (x0 + pxl < WO)
                    *reinterpret_cast<float2*>(orow) = make_float2(v[0], v[1]);
                if (x0 + pxl + 2 < WO)
                    *reinterpret_cast<float2*>(orow + 2) = make_float2(v[2], v[3]);
            }
        }
    }
}

// ---------------- launch -----------------------------------------------------
extern "C" void kernel_launch(void* const* d_in, const int* in_sizes, int n_in,
                              void* d_out, int out_size) {
    const float* x    = (const float*)d_in[0];
    const float* w    = (const float*)d_in[1];
    const float* bias = (const float*)d_in[2];
    float* out = (float*)d_out;

    setup_kernel<<<289, 256>>>(x, w, bias);
    conv_kernel<<<dim3(3, 95, 64), 256>>>(x, out);
}

// round 4
// speedup vs baseline: 2.3226x; 1.0009x over previous
#include <cuda_runtime.h>
#include <cstdint>

#define B_N  32
#define C_IN 64
#define H    192
#define W    192
#define HO   190
#define WO   190
#define OC   128
#define HW   (H*W)

// ---------------- device scratch (no allocations allowed) -------------------
__device__ float g_valid[B_N][4];        // 1.0 if fixation valid else 0.0
__device__ float g_bsum[B_N][OC];        // sum_f valid[b,f]*bias[f,oc]
__device__ float g_wT[C_IN * 9 * OC];    // wT[(c*9+kk)*128 + oc]

// NaN test immune to fast-math
__device__ __forceinline__ bool is_nan_bits(float v) {
    unsigned u = __float_as_uint(v);
    return (u & 0x7fffffffu) > 0x7f800000u;
}

// ---------------- packed f32x2 helpers --------------------------------------
typedef unsigned long long u64;

__device__ __forceinline__ u64 pack2(float lo, float hi) {
    u64 r;
    asm("mov.b64 %0, {%1, %2};" : "=l"(r) : "f"(lo), "f"(hi));
    return r;
}
__device__ __forceinline__ void unpack2(u64 v, float& lo, float& hi) {
    asm("mov.b64 {%0, %1}, %2;" : "=f"(lo), "=f"(hi) : "l"(v));
}
__device__ __forceinline__ void ffma2(u64& d, u64 a, u64 b) {
    asm("fma.rn.f32x2 %0, %1, %2, %0;" : "+l"(d) : "l"(a), "l"(b));
}

// ---------------- setup: validity + bias sums + weight transpose ------------
// grid 289 blocks x 256: blocks 0..287 transpose weights, block 288 does prep.
__global__ void setup_kernel(const float* __restrict__ x,
                             const float* __restrict__ w,
                             const float* __restrict__ bias) {
    int t = threadIdx.x;
    if (blockIdx.x < 288) {
        int i = blockIdx.x * 256 + t;                // 73728 weights exactly
        int oc = i & 127;
        int kk = (i >> 7) % 9;
        int c  = i / (9 * 128);
        int f = c & 3, j = c >> 2;
        // weight[f][oc][j][ky][kx] -> g_wT[(c*9+kk)*128 + oc]
        g_wT[i] = w[f * 18432 + oc * 144 + j * 9 + kk];
    } else {
        __shared__ float sval[B_N][4];
        if (t < B_N * 4) {
            int b = t >> 2, f = t & 3;
            float v = x[(size_t)(b * C_IN + f) * HW];     // marker at (0,0)
            float val = is_nan_bits(v) ? 0.f : 1.f;
            g_valid[b][f] = val;
            sval[b][f] = val;
        }
        __syncthreads();
        for (int i = t; i < B_N * OC; i += 256) {
            int b = i >> 7, oc = i & 127;
            float s = 0.f;
#pragma unroll
            for (int f = 0; f < 4; f++) s += sval[b][f] * bias[f * OC + oc];
            g_bsum[b][oc] = s;
        }
    }
}

// ---------------- main conv: 64px x 64oc x 2rows tile, pipelined ------------
// grid = (3 x-tiles, 95 row-pairs, 32 batches * 2 oc-tiles), block = 256
__global__ void __launch_bounds__(256, 2)
conv_kernel(const float* __restrict__ x, float* __restrict__ out) {
    const int x0  = blockIdx.x * 64;          // 0, 64, 128
    const int y0  = blockIdx.y * 2;           // output rows y0, y0+1
    const int b   = blockIdx.z >> 1;
    const int oc0 = (blockIdx.z & 1) * 64;

    __shared__ float Ws[2][9][64];            // double-buffered weight slice
    __shared__ float Xs[2][4][66];            // double-buffered 4 input rows
    __shared__ float vm[4];

    const int t   = threadIdx.x;
    const int tx  = t & 15;
    const int ty  = t >> 4;
    const int pxl = tx * 4;                   // local pixel base
    const int ocl = ty * 4;                   // local oc base

    const int nload = min(66, W - x0);        // 66,66,64
    const int irow  = t / 66;                 // input-load row   (t<264)
    const int icol  = t - irow * 66;          // input-load col

    const float* xb = x + (size_t)b * C_IN * HW + (size_t)y0 * W + x0;

    if (t < 4) vm[t] = g_valid[b][t];
    __syncthreads();

    float w0, w1, w2 = 0.f, xv0, xv1;

    // -------- prologue: load channel 0 into buffer 0 --------
    {
        const float* wsrc = g_wT + oc0;       // channel 0
        w0 = wsrc[(t >> 6) * 128 + (t & 63)];
        w1 = wsrc[((t >> 6) + 4) * 128 + (t & 63)];
        if (t < 64) w2 = wsrc[8 * 128 + t];
        float vmf = vm[0];
        float v = 0.f;
        if (t < 264 && icol < nload) {
            v = xb[irow * W + icol];
            v = is_nan_bits(v) ? 0.f : v;
            v *= vmf;
        }
        xv0 = v;
        v = 0.f;
        if (t < 8 && (t + 58) < nload) {
            v = xb[3 * W + t + 58];
            v = is_nan_bits(v) ? 0.f : v;
            v *= vmf;
        }
        xv1 = v;

        float* Wn = (float*)Ws[0];
        float* Xn = (float*)Xs[0];
        Wn[t] = w0; Wn[t + 256] = w1;
        if (t < 64) Wn[t + 512] = w2;
        if (t < 264) Xn[t] = xv0;
        if (t < 8)   Xn[t + 256] = xv1;
    }
    __syncthreads();

    // acc[y][p][q]: row y0+y, pixel pxl+p, oc pair (ocl+2q, ocl+2q+1)
    u64 acc[2][4][2];
#pragma unroll
    for (int yy = 0; yy < 2; yy++)
#pragma unroll
        for (int p = 0; p < 4; p++) { acc[yy][p][0] = 0ull; acc[yy][p][1] = 0ull; }

#pragma unroll 1
    for (int c = 0; c < C_IN; c++) {
        const int buf = c & 1;
        const int cn  = c + 1;

        // -------- prefetch channel c+1 into registers --------
        if (cn < C_IN) {
            const float* wsrc = g_wT + cn * 9 * 128 + oc0;
            w0 = wsrc[(t >> 6) * 128 + (t & 63)];
            w1 = wsrc[((t >> 6) + 4) * 128 + (t & 63)];
            if (t < 64) w2 = wsrc[8 * 128 + t];
            const float* xc = xb + (size_t)cn * HW;
            float vmf = vm[cn & 3];
            float v = 0.f;
            if (t < 264 && icol < nload) {
                v = xc[irow * W + icol];
                v = is_nan_bits(v) ? 0.f : v;
                v *= vmf;
            }
            xv0 = v;
            v = 0.f;
            if (t < 8 && (t + 58) < nload) {
                v = xc[3 * W + t + 58];
                v = is_nan_bits(v) ? 0.f : v;
                v *= vmf;
            }
            xv1 = v;
        }

        // -------- compute channel c --------
        const float (*Wb)[64] = Ws[buf];
        const float (*Xb)[66] = Xs[buf];
#pragma unroll
        for (int ky = 0; ky < 3; ky++) {
            u64 s[2][6];
#pragma unroll
            for (int yy = 0; yy < 2; yy++)
#pragma unroll
                for (int i = 0; i < 6; i++) {
                    float v = Xb[ky + yy][pxl + i];
                    s[yy][i] = pack2(v, v);
                }
#pragma unroll
            for (int kx = 0; kx < 3; kx++) {
                const u64* ap = reinterpret_cast<const u64*>(&Wb[ky * 3 + kx][ocl]);
                u64 a0 = ap[0];
                u64 a1 = ap[1];
#pragma unroll
                for (int yy = 0; yy < 2; yy++)
#pragma unroll
                    for (int p = 0; p < 4; p++) {
                        ffma2(acc[yy][p][0], a0, s[yy][kx + p]);
                        ffma2(acc[yy][p][1], a1, s[yy][kx + p]);
                    }
            }
        }

        // -------- store prefetch into the other buffer --------
        if (cn < C_IN) {
            float* Wn = (float*)Ws[buf ^ 1];
            float* Xn = (float*)Xs[buf ^ 1];
            Wn[t] = w0; Wn[t + 256] = w1;
            if (t < 64) Wn[t + 512] = w2;
            if (t < 264) Xn[t] = xv0;
            if (t < 8)   Xn[t + 256] = xv1;
        }
        __syncthreads();
    }

    // ---------------- epilogue: add masked bias, store -----------------------
    float bs[4];
#pragma unroll
    for (int i = 0; i < 4; i++) bs[i] = g_bsum[b][oc0 + ocl + i];

#pragma unroll
    for (int yy = 0; yy < 2; yy++) {
        const int yrow = y0 + yy;
#pragma unroll
        for (int q = 0; q < 2; q++) {
#pragma unroll
            for (int hh = 0; hh < 2; hh++) {
                int oc = oc0 + ocl + 2 * q + hh;
                float* orow = out + ((size_t)(b * OC + oc) * HO + yrow) * WO + x0 + pxl;
                float v[4];
#pragma unroll
                for (int p = 0; p < 4; p++) {
                    float lo, hi;
                    unpack2(acc[yy][p][q], lo, hi);
                    v[p] = (hh == 0 ? lo : hi) + bs[2 * q + hh];
                }
                if (x0 + pxl < WO)
                    *reinterpret_cast<float2*>(orow) = make_float2(v[0], v[1]);
                if (x0 + pxl + 2 < WO)
                    *reinterpret_cast<float2*>(orow + 2) = make_float2(v[2], v[3]);
            }
        }
    }
}

// ---------------- launch -----------------------------------------------------
extern "C" void kernel_launch(void* const* d_in, const int* in_sizes, int n_in,
                              void* d_out, int out_size) {
    const float* x    = (const float*)d_in[0];
    const float* w    = (const float*)d_in[1];
    const float* bias = (const float*)d_in[2];
    float* out = (float*)d_out;

    setup_kernel<<<289, 256>>>(x, w, bias);
    conv_kernel<<<dim3(3, 95, 64), 256>>>(x, out);
}

// round 6
// speedup vs baseline: 9.1380x; 3.9344x over previous
#include <cuda_runtime.h>
#include <cstdint>

#define B_N  32
#define C_IN 64
#define H    192
#define W    192
#define HO   190
#define WO   190
#define OC   128
#define HW   (H*W)

#define XS_STRIDE 104     // floats; 104 mod 32 = 8 -> conflict-free B-fragment LDS

// ---------------- device scratch (no allocations allowed) -------------------
__device__ float g_valid[B_N][4];
__device__ float g_bsum[B_N][OC];
// A-fragment-ordered weights: [tap][chunk][slab][oct][lane][4]  (73728 floats)
__device__ __align__(16) float g_wA[9 * 8 * 4 * 2 * 32 * 4];

__device__ __forceinline__ bool is_nan_bits(float v) {
    unsigned u = __float_as_uint(v);
    return (u & 0x7fffffffu) > 0x7f800000u;
}
__device__ __forceinline__ unsigned f2tf32(float v) {
    unsigned r;
    asm("cvt.rna.tf32.f32 %0, %1;" : "=r"(r) : "f"(v));
    return r;
}

#define MMA_TF32(d, a, b0, b1) \
    asm volatile("mma.sync.aligned.m16n8k8.row.col.f32.tf32.tf32.f32 " \
        "{%0,%1,%2,%3},{%4,%5,%6,%7},{%8,%9},{%0,%1,%2,%3};" \
        : "+f"((d)[0]), "+f"((d)[1]), "+f"((d)[2]), "+f"((d)[3]) \
        : "r"((a).x), "r"((a).y), "r"((a).z), "r"((a).w), "r"(b0), "r"(b1))

// ---------------- setup: validity + bias + fragment-ordered weights ---------
// blocks 0..287: weights, block 288: validity + bias sums.
__global__ void setup_kernel(const float* __restrict__ x,
                             const float* __restrict__ w,
                             const float* __restrict__ bias) {
    int t = threadIdx.x;
    if (blockIdx.x < 288) {
        int i = blockIdx.x * 256 + t;            // 0..73727
        int a    = i & 3;
        int lane = (i >> 2) & 31;
        int r2   = i >> 7;
        int oct  = r2 & 1;
        int slab = (r2 >> 1) & 3;
        int chunk= (r2 >> 3) & 7;
        int tap  = r2 >> 6;                      // ky*3 + kx
        // PTX tf32 m16n8k8 A fragment: a0:(m,c) a1:(m+8,c) a2:(m,c+4) a3:(m+8,c+4)
        int row = (lane >> 2) + (a & 1) * 8;     // m within 16-row tile
        int col = (lane & 3) + ((a >> 1) & 1) * 4;  // k within 8
        int oc  = slab * 32 + oct * 16 + row;
        int c   = chunk * 8 + col;               // dense channel index
        int f = c & 3, j = c >> 2;
        float v = w[f * 18432 + oc * 144 + j * 9 + tap];
        g_wA[i] = __uint_as_float(f2tf32(v));
    } else {
        __shared__ float sval[B_N][4];
        if (t < B_N * 4) {
            int b = t >> 2, f = t & 3;
            float v = x[(size_t)(b * C_IN + f) * HW];   // marker at (0,0)
            float val = is_nan_bits(v) ? 0.f : 1.f;
            g_valid[b][f] = val;
            sval[b][f] = val;
        }
        __syncthreads();
        for (int i = t; i < B_N * OC; i += 256) {
            int b = i >> 7, oc = i & 127;
            float s = 0.f;
#pragma unroll
            for (int f = 0; f < 4; f++) s += sval[b][f] * bias[f * OC + oc];
            g_bsum[b][oc] = s;
        }
    }
}

// ---------------- main conv: tf32 mma.sync implicit GEMM --------------------
// grid = (2 x-tiles, 190 rows, 32 batches), block = 256 (8 warps)
// Block tile: 128 oc x 96 px. Warp: 32 oc x 48 px (4 slabs x 2 halves).
__global__ void __launch_bounds__(256, 2)
conv_kernel(const float* __restrict__ x, float* __restrict__ out) {
    __shared__ float Xs[C_IN][XS_STRIDE];     // one input row, all 64 ch, 98 px
    __shared__ float vm[4];

    const int x0 = blockIdx.x * 94;           // 0 or 94 (tiles overlap 2 px)
    const int y  = blockIdx.y;
    const int b  = blockIdx.z;

    const int t    = threadIdx.x;
    const int warp = t >> 5;
    const int lane = t & 31;
    const int slab = warp >> 1;               // 0..3 -> oc slab of 32
    const int nb   = (warp & 1) * 48;         // px half

    if (t < 4) vm[t] = g_valid[b][t];

    const float* xb = x + (size_t)b * C_IN * HW + (size_t)y * W + x0;

    // acc[oct][nt][4]
    float acc[2][6][4];
#pragma unroll
    for (int o = 0; o < 2; o++)
#pragma unroll
        for (int nt = 0; nt < 6; nt++)
#pragma unroll
            for (int q = 0; q < 4; q++) acc[o][nt][q] = 0.f;

    const uint4* wbase = reinterpret_cast<const uint4*>(g_wA);

#pragma unroll 1
    for (int ky = 0; ky < 3; ky++) {
        // ---- stage input row y+ky: 64 ch x 98 px, masked + tf32-rounded ----
        __syncthreads();
        {
            const float* xrow = xb + (size_t)ky * W;
#pragma unroll
            for (int r = 0; r < 8; r++) {
                int c = warp + r * 8;                 // warp-coalesced rows
                const float* src = xrow + (size_t)c * HW;
                float vmf = vm[c & 3];
#pragma unroll
                for (int q = 0; q < 4; q++) {
                    int col = lane + q * 32;
                    if (col < 98) {
                        float v = src[col];
                        v = is_nan_bits(v) ? 0.f : v;
                        Xs[c][col] = __uint_as_float(f2tf32(v * vmf));
                    }
                }
            }
        }
        __syncthreads();

#pragma unroll 1
        for (int kx = 0; kx < 3; kx++) {
            const int tap = ky * 3 + kx;
            const uint4* wp = wbase + (size_t)(tap * 32 + slab) * 64 + lane;
            const float* xr = &Xs[lane & 3][kx + nb + (lane >> 2)];

            uint4 an0 = wp[0];          // prefetch chunk 0
            uint4 an1 = wp[32];

#pragma unroll 1
            for (int ch = 0; ch < 8; ch++) {
                uint4 a0 = an0, a1 = an1;
                if (ch < 7) {                         // prefetch next chunk
                    an0 = wp[(ch + 1) * 256];
                    an1 = wp[(ch + 1) * 256 + 32];
                }
                const float* xr0 = xr + ch * (8 * XS_STRIDE);
#pragma unroll
                for (int nt = 0; nt < 6; nt++) {
                    unsigned b0 = __float_as_uint(xr0[nt * 8]);
                    unsigned b1 = __float_as_uint(xr0[4 * XS_STRIDE + nt * 8]);
                    MMA_TF32(acc[0][nt], a0, b0, b1);
                    MMA_TF32(acc[1][nt], a1, b0, b1);
                }
            }
        }
    }

    // ---- epilogue: bias + store ------------------------------------------
    // D frag: d0:(m,2c) d1:(m,2c+1) d2:(m+8,2c) d3:(m+8,2c+1)
    const int mrow = lane >> 2;
    const int ncol = 2 * (lane & 3);
#pragma unroll
    for (int oct = 0; oct < 2; oct++) {
        int ocb = slab * 32 + oct * 16 + mrow;
        float bsA = g_bsum[b][ocb];
        float bsB = g_bsum[b][ocb + 8];
        float* o0 = out + ((size_t)(b * OC + ocb) * HO + y) * WO + x0 + nb + ncol;
        float* o1 = o0 + (size_t)8 * HO * WO;
#pragma unroll
        for (int nt = 0; nt < 6; nt++) {
            *reinterpret_cast<float2*>(o0 + nt * 8) =
                make_float2(acc[oct][nt][0] + bsA, acc[oct][nt][1] + bsA);
            *reinterpret_cast<float2*>(o1 + nt * 8) =
                make_float2(acc[oct][nt][2] + bsB, acc[oct][nt][3] + bsB);
        }
    }
}

// ---------------- launch -----------------------------------------------------
extern "C" void kernel_launch(void* const* d_in, const int* in_sizes, int n_in,
                              void* d_out, int out_size) {
    const float* x    = (const float*)d_in[0];
    const float* w    = (const float*)d_in[1];
    const float* bias = (const float*)d_in[2];
    float* out = (float*)d_out;

    setup_kernel<<<289, 256>>>(x, w, bias);
    conv_kernel<<<dim3(2, HO, B_N), 256>>>(x, out);
}